// round 1
// baseline (speedup 1.0000x reference)
#include <cuda_runtime.h>
#include <cuda_bf16.h>

#define NN 50000
#define EE 500000
#define GG 128
#define SCAN_B 512
#define NBLK ((NN + SCAN_B - 1) / SCAN_B)   // 98

// ---------------- scratch (static device allocations) ----------------
__device__ float g_deg[NN];
__device__ float g_dinv[NN];
__device__ int   g_count[NN];
__device__ int   g_rowstart[NN + 1];
__device__ int   g_cursor[NN];
__device__ int   g_part[NBLK];
__device__ int   g_esrc[EE];
__device__ float g_ew[EE];

__device__ float g_T1[NN * 160];
__device__ float g_T2[NN * 160];
__device__ float g_H1[NN * 128];
__device__ float g_H2[NN * 64];
__device__ float g_H3[NN * 32];
__device__ float g_pool[GG * 32];
__device__ float g_cntg[GG];

// ---------------- preprocessing ----------------
__global__ void zero_kernel() {
    int i = blockIdx.x * blockDim.x + threadIdx.x;
    if (i < NN) { g_deg[i] = 0.f; g_count[i] = 0; }
    if (i < GG * 32) g_pool[i] = 0.f;
    if (i < GG) g_cntg[i] = 0.f;
}

__global__ void edge_deg_kernel(const int* __restrict__ src, const int* __restrict__ dst,
                                const float* __restrict__ ea) {
    int e = blockIdx.x * blockDim.x + threadIdx.x;
    if (e >= EE) return;
    atomicAdd(&g_deg[src[e]], ea[e]);
    atomicAdd(&g_count[dst[e]], 1);
}

__global__ void dinv_kernel() {
    int i = blockIdx.x * blockDim.x + threadIdx.x;
    if (i >= NN) return;
    float d = g_deg[i];
    g_dinv[i] = (d > 0.f) ? rsqrtf(d) : 0.f;
}

// exclusive scan of g_count -> g_rowstart (3 phases)
__global__ void scan1_kernel() {
    __shared__ int s[SCAN_B];
    int t = threadIdx.x;
    int i = blockIdx.x * SCAN_B + t;
    int v = (i < NN) ? g_count[i] : 0;
    s[t] = v;
    __syncthreads();
    for (int off = 1; off < SCAN_B; off <<= 1) {
        int add = (t >= off) ? s[t - off] : 0;
        __syncthreads();
        s[t] += add;
        __syncthreads();
    }
    if (i < NN) g_rowstart[i] = s[t] - v;   // exclusive
    if (t == SCAN_B - 1) g_part[blockIdx.x] = s[t];
}

__global__ void scan2_kernel() {
    if (threadIdx.x == 0) {
        int run = 0;
        for (int i = 0; i < NBLK; i++) { int v = g_part[i]; g_part[i] = run; run += v; }
    }
}

__global__ void scan3_kernel() {
    int i = blockIdx.x * blockDim.x + threadIdx.x;
    if (i < NN) {
        int v = g_rowstart[i] + g_part[i / SCAN_B];
        g_rowstart[i] = v;
        g_cursor[i] = v;
    }
    if (i == 0) g_rowstart[NN] = EE;
}

__global__ void edge_scatter_kernel(const int* __restrict__ src, const int* __restrict__ dst,
                                    const float* __restrict__ ea) {
    int e = blockIdx.x * blockDim.x + threadIdx.x;
    if (e >= EE) return;
    int s = src[e], d = dst[e];
    float w = -g_dinv[s] * ea[e] * g_dinv[d];
    int pos = atomicAdd(&g_cursor[d], 1);
    g_esrc[pos] = s;
    g_ew[pos] = w;
}

// ---------------- sparse propagate: out[n] = sum_j w_j * X[src_j]  (CSR by dst) ----------------
template <int F, bool SECOND>
__global__ void prop_kernel(const float* __restrict__ X, const float* __restrict__ T0,
                            float* __restrict__ out) {
    int node = blockIdx.x;
    int f = threadIdx.x;
    int s = g_rowstart[node], e = g_rowstart[node + 1];
    float a0 = 0.f, a1 = 0.f;
    int j = s;
    for (; j + 1 < e; j += 2) {
        a0 += g_ew[j]     * X[(long)g_esrc[j]     * F + f];
        a1 += g_ew[j + 1] * X[(long)g_esrc[j + 1] * F + f];
    }
    if (j < e) a0 += g_ew[j] * X[(long)g_esrc[j] * F + f];
    float v = a0 + a1;
    if (SECOND) v = 2.f * v - T0[(long)node * F + f];
    out[(long)node * F + f] = v;
}

// ---------------- fused 3-term GEMM: out = relu(T0@W0 + T1@W1 + T2@W2 + b) ----------------
template <int FIN, int FOUT>
__global__ void __launch_bounds__(256)
gemm3_kernel(const float* __restrict__ A0, const float* __restrict__ A1,
             const float* __restrict__ A2, const float* __restrict__ W,
             const float* __restrict__ bias, float* __restrict__ out) {
    constexpr int BM = 64, BK = 32, THREADS = 256;
    constexpr int TN = (FOUT >= 128) ? 8 : 4;
    constexpr int CT = FOUT / TN;            // threads along cols
    constexpr int RT = THREADS / CT;         // threads along rows
    constexpr int TM = BM / RT;

    __shared__ float As[BK * BM];            // transposed: As[k][m]
    __shared__ float Bs[BK * FOUT];          // Bs[k][c]

    int tid = threadIdx.x;
    int row0 = blockIdx.x * BM;
    int tx = tid % CT, ty = tid / CT;

    float acc[TM][TN];
#pragma unroll
    for (int i = 0; i < TM; i++)
#pragma unroll
        for (int jj = 0; jj < TN; jj++) acc[i][jj] = 0.f;

    for (int k0 = 0; k0 < 3 * FIN; k0 += BK) {
        const float* A = (k0 < FIN) ? A0 : (k0 < 2 * FIN ? A1 : A2);
        int kk = k0 % FIN;
        // A tile: BM x BK -> store transposed. 512 float4, 2 per thread.
#pragma unroll
        for (int l = 0; l < 2; l++) {
            int idx = l * 256 + tid;
            int r = idx >> 3;
            int k4 = (idx & 7) * 4;
            float4 v = make_float4(0.f, 0.f, 0.f, 0.f);
            int grow = row0 + r;
            if (grow < NN) v = *(const float4*)&A[(long)grow * FIN + kk + k4];
            As[(k4 + 0) * BM + r] = v.x;
            As[(k4 + 1) * BM + r] = v.y;
            As[(k4 + 2) * BM + r] = v.z;
            As[(k4 + 3) * BM + r] = v.w;
        }
        // B tile: BK x FOUT contiguous in W
#pragma unroll
        for (int l = 0; l < FOUT / 32; l++) {
            int idx = l * 256 + tid;
            ((float4*)Bs)[idx] = *(const float4*)&W[(long)k0 * FOUT + idx * 4];
        }
        __syncthreads();
#pragma unroll
        for (int k = 0; k < BK; k++) {
            float a[TM], b[TN];
#pragma unroll
            for (int i = 0; i < TM; i++) a[i] = As[k * BM + ty * TM + i];
#pragma unroll
            for (int jj = 0; jj < TN; jj++) b[jj] = Bs[k * FOUT + tx * TN + jj];
#pragma unroll
            for (int i = 0; i < TM; i++)
#pragma unroll
                for (int jj = 0; jj < TN; jj++) acc[i][jj] = fmaf(a[i], b[jj], acc[i][jj]);
        }
        __syncthreads();
    }
#pragma unroll
    for (int i = 0; i < TM; i++) {
        int r = row0 + ty * TM + i;
        if (r < NN) {
#pragma unroll
            for (int jj = 0; jj < TN; jj++) {
                float v = acc[i][jj] + bias[tx * TN + jj];
                out[(long)r * FOUT + tx * TN + jj] = fmaxf(v, 0.f);
            }
        }
    }
}

// ---------------- pooling + final linear ----------------
__global__ void pool_kernel(const int* __restrict__ batch) {
    int n = blockIdx.x * blockDim.x + threadIdx.x;
    if (n >= NN) return;
    int g = batch[n];
    const float* h = g_H3 + (long)n * 32;
#pragma unroll
    for (int f = 0; f < 32; f++) atomicAdd(&g_pool[g * 32 + f], h[f]);
    atomicAdd(&g_cntg[g], 1.f);
}

__global__ void final_kernel(const float* __restrict__ Wl, const float* __restrict__ bl,
                             float* __restrict__ out) {
    int t = threadIdx.x;
    if (t >= GG * 2) return;
    int g = t >> 1, c = t & 1;
    float cnt = fmaxf(g_cntg[g], 1.f);
    float inv = 1.f / cnt;
    float s = bl[c];
#pragma unroll
    for (int f = 0; f < 32; f++) s += (g_pool[g * 32 + f] * inv) * Wl[f * 2 + c];
    out[g * 2 + c] = s;
}

// ---------------- driver ----------------
extern "C" void kernel_launch(void* const* d_in, const int* in_sizes, int n_in,
                              void* d_out, int out_size) {
    const float* x     = (const float*)d_in[0];
    const int*   ei    = (const int*)d_in[1];
    const float* ea    = (const float*)d_in[2];
    const int*   batch = (const int*)d_in[3];
    const float* W1 = (const float*)d_in[4];
    const float* b1 = (const float*)d_in[5];
    const float* W2 = (const float*)d_in[6];
    const float* b2 = (const float*)d_in[7];
    const float* W3 = (const float*)d_in[8];
    const float* b3 = (const float*)d_in[9];
    const float* Wl = (const float*)d_in[10];
    const float* bl = (const float*)d_in[11];
    float* out = (float*)d_out;

    const int* src = ei;
    const int* dst = ei + EE;

    float *T1, *T2, *H1, *H2, *H3;
    cudaGetSymbolAddress((void**)&T1, g_T1);
    cudaGetSymbolAddress((void**)&T2, g_T2);
    cudaGetSymbolAddress((void**)&H1, g_H1);
    cudaGetSymbolAddress((void**)&H2, g_H2);
    cudaGetSymbolAddress((void**)&H3, g_H3);

    int nb = (NN + 255) / 256;
    int eb = (EE + 255) / 256;

    zero_kernel<<<nb, 256>>>();
    edge_deg_kernel<<<eb, 256>>>(src, dst, ea);
    dinv_kernel<<<nb, 256>>>();
    scan1_kernel<<<NBLK, SCAN_B>>>();
    scan2_kernel<<<1, 32>>>();
    scan3_kernel<<<nb, 256>>>();
    edge_scatter_kernel<<<eb, 256>>>(src, dst, ea);

    // Layer 1: 160 -> 128
    prop_kernel<160, false><<<NN, 160>>>(x, nullptr, T1);
    prop_kernel<160, true ><<<NN, 160>>>(T1, x, T2);
    gemm3_kernel<160, 128><<<(NN + 63) / 64, 256>>>(x, T1, T2, W1, b1, H1);

    // Layer 2: 128 -> 64
    prop_kernel<128, false><<<NN, 128>>>(H1, nullptr, T1);
    prop_kernel<128, true ><<<NN, 128>>>(T1, H1, T2);
    gemm3_kernel<128, 64><<<(NN + 63) / 64, 256>>>(H1, T1, T2, W2, b2, H2);

    // Layer 3: 64 -> 32
    prop_kernel<64, false><<<NN, 64>>>(H2, nullptr, T1);
    prop_kernel<64, true ><<<NN, 64>>>(T1, H2, T2);
    gemm3_kernel<64, 32><<<(NN + 63) / 64, 256>>>(H2, T1, T2, W3, b3, H3);

    // Pool + linear
    pool_kernel<<<nb, 256>>>(batch);
    final_kernel<<<1, 256>>>(Wl, bl, out);
}

// round 2
// speedup vs baseline: 2.1086x; 2.1086x over previous
#include <cuda_runtime.h>
#include <cuda_bf16.h>

#define NN 50000
#define EE 500000
#define GG 128
#define SCAN_B 512
#define NBLK ((NN + SCAN_B - 1) / SCAN_B)   // 98

// ---------------- scratch (static device allocations) ----------------
__device__ float g_deg[NN];
__device__ float g_dinv[NN];
__device__ int   g_count[NN];
__device__ int   g_rowstart[NN + 1];
__device__ int   g_cursor[NN];
__device__ int   g_part[NBLK];
__device__ int   g_esrc[EE];
__device__ float g_ew[EE];

__device__ float g_T1[NN * 160];
__device__ float g_T2[NN * 160];
__device__ float g_H1[NN * 128];
__device__ float g_H2[NN * 64];
__device__ float g_H3[NN * 32];
__device__ float g_pool[GG * 32];
__device__ float g_cntg[GG];

// ---------------- preprocessing ----------------
__global__ void zero_kernel() {
    int i = blockIdx.x * blockDim.x + threadIdx.x;
    if (i < NN) { g_deg[i] = 0.f; g_count[i] = 0; }
    if (i < GG * 32) g_pool[i] = 0.f;
    if (i < GG) g_cntg[i] = 0.f;
}

__global__ void edge_deg_kernel(const int* __restrict__ src, const int* __restrict__ dst,
                                const float* __restrict__ ea) {
    int e = blockIdx.x * blockDim.x + threadIdx.x;
    if (e >= EE) return;
    atomicAdd(&g_deg[src[e]], ea[e]);
    atomicAdd(&g_count[dst[e]], 1);
}

__global__ void dinv_kernel() {
    int i = blockIdx.x * blockDim.x + threadIdx.x;
    if (i >= NN) return;
    float d = g_deg[i];
    g_dinv[i] = (d > 0.f) ? rsqrtf(d) : 0.f;
}

__global__ void scan1_kernel() {
    __shared__ int s[SCAN_B];
    int t = threadIdx.x;
    int i = blockIdx.x * SCAN_B + t;
    int v = (i < NN) ? g_count[i] : 0;
    s[t] = v;
    __syncthreads();
    for (int off = 1; off < SCAN_B; off <<= 1) {
        int add = (t >= off) ? s[t - off] : 0;
        __syncthreads();
        s[t] += add;
        __syncthreads();
    }
    if (i < NN) g_rowstart[i] = s[t] - v;   // exclusive within block
    if (t == SCAN_B - 1) g_part[blockIdx.x] = s[t];
}

__global__ void scan2_kernel() {
    __shared__ int s[128];
    int t = threadIdx.x;
    int v = (t < NBLK) ? g_part[t] : 0;
    s[t] = v;
    __syncthreads();
    for (int off = 1; off < 128; off <<= 1) {
        int a = (t >= off) ? s[t - off] : 0;
        __syncthreads();
        s[t] += a;
        __syncthreads();
    }
    if (t < NBLK) g_part[t] = s[t] - v;     // exclusive block offsets
}

__global__ void scan3_kernel() {
    int i = blockIdx.x * blockDim.x + threadIdx.x;
    if (i < NN) {
        int v = g_rowstart[i] + g_part[i / SCAN_B];
        g_rowstart[i] = v;
        g_cursor[i] = v;
    }
    if (i == 0) g_rowstart[NN] = EE;
}

__global__ void edge_scatter_kernel(const int* __restrict__ src, const int* __restrict__ dst,
                                    const float* __restrict__ ea) {
    int e = blockIdx.x * blockDim.x + threadIdx.x;
    if (e >= EE) return;
    int s = src[e], d = dst[e];
    float w = -g_dinv[s] * ea[e] * g_dinv[d];
    int pos = atomicAdd(&g_cursor[d], 1);
    g_esrc[pos] = s;
    g_ew[pos] = w;
}

// ---------------- sparse propagate: warp per node, vectorized ----------------
__device__ __forceinline__ void fma4(float4& a, float w, float4 v) {
    a.x = fmaf(w, v.x, a.x); a.y = fmaf(w, v.y, a.y);
    a.z = fmaf(w, v.z, a.z); a.w = fmaf(w, v.w, a.w);
}

// F=160: 40 float4 per row. lane handles idx lane, plus lane+32 for lane<8.
template <bool SECOND>
__global__ void __launch_bounds__(256)
prop160_kernel(const float* __restrict__ X, const float* __restrict__ T0,
               float* __restrict__ out) {
    int node = (blockIdx.x << 3) + (threadIdx.x >> 5);
    if (node >= NN) return;
    int lane = threadIdx.x & 31;
    int s = g_rowstart[node], e = g_rowstart[node + 1];
    const float4* X4 = (const float4*)X;
    float4 a0 = {0,0,0,0}, a1 = {0,0,0,0}, b0 = {0,0,0,0}, b1 = {0,0,0,0};
    int j = s;
    for (; j + 1 < e; j += 2) {
        float w0 = g_ew[j], w1 = g_ew[j + 1];
        long r0 = (long)g_esrc[j] * 40, r1 = (long)g_esrc[j + 1] * 40;
        fma4(a0, w0, X4[r0 + lane]);
        fma4(a1, w1, X4[r1 + lane]);
        if (lane < 8) {
            fma4(b0, w0, X4[r0 + 32 + lane]);
            fma4(b1, w1, X4[r1 + 32 + lane]);
        }
    }
    if (j < e) {
        float w0 = g_ew[j];
        long r0 = (long)g_esrc[j] * 40;
        fma4(a0, w0, X4[r0 + lane]);
        if (lane < 8) fma4(b0, w0, X4[r0 + 32 + lane]);
    }
    a0.x += a1.x; a0.y += a1.y; a0.z += a1.z; a0.w += a1.w;
    b0.x += b1.x; b0.y += b1.y; b0.z += b1.z; b0.w += b1.w;
    long o = (long)node * 40;
    const float4* T04 = (const float4*)T0;
    float4* O4 = (float4*)out;
    if (SECOND) {
        float4 t = T04[o + lane];
        a0.x = 2.f*a0.x - t.x; a0.y = 2.f*a0.y - t.y; a0.z = 2.f*a0.z - t.z; a0.w = 2.f*a0.w - t.w;
    }
    O4[o + lane] = a0;
    if (lane < 8) {
        if (SECOND) {
            float4 t = T04[o + 32 + lane];
            b0.x = 2.f*b0.x - t.x; b0.y = 2.f*b0.y - t.y; b0.z = 2.f*b0.z - t.z; b0.w = 2.f*b0.w - t.w;
        }
        O4[o + 32 + lane] = b0;
    }
}

// F=128: 32 float4 per row, one per lane.
template <bool SECOND>
__global__ void __launch_bounds__(256)
prop128_kernel(const float* __restrict__ X, const float* __restrict__ T0,
               float* __restrict__ out) {
    int node = (blockIdx.x << 3) + (threadIdx.x >> 5);
    if (node >= NN) return;
    int lane = threadIdx.x & 31;
    int s = g_rowstart[node], e = g_rowstart[node + 1];
    const float4* X4 = (const float4*)X;
    float4 a0 = {0,0,0,0}, a1 = {0,0,0,0};
    int j = s;
    for (; j + 1 < e; j += 2) {
        fma4(a0, g_ew[j],     X4[(long)g_esrc[j]     * 32 + lane]);
        fma4(a1, g_ew[j + 1], X4[(long)g_esrc[j + 1] * 32 + lane]);
    }
    if (j < e) fma4(a0, g_ew[j], X4[(long)g_esrc[j] * 32 + lane]);
    a0.x += a1.x; a0.y += a1.y; a0.z += a1.z; a0.w += a1.w;
    long o = (long)node * 32 + lane;
    if (SECOND) {
        float4 t = ((const float4*)T0)[o];
        a0.x = 2.f*a0.x - t.x; a0.y = 2.f*a0.y - t.y; a0.z = 2.f*a0.z - t.z; a0.w = 2.f*a0.w - t.w;
    }
    ((float4*)out)[o] = a0;
}

// F=64: 32 float2 per row, one per lane.
template <bool SECOND>
__global__ void __launch_bounds__(256)
prop64_kernel(const float* __restrict__ X, const float* __restrict__ T0,
              float* __restrict__ out) {
    int node = (blockIdx.x << 3) + (threadIdx.x >> 5);
    if (node >= NN) return;
    int lane = threadIdx.x & 31;
    int s = g_rowstart[node], e = g_rowstart[node + 1];
    const float2* X2 = (const float2*)X;
    float2 a0 = {0,0}, a1 = {0,0};
    int j = s;
    for (; j + 1 < e; j += 2) {
        float w0 = g_ew[j], w1 = g_ew[j + 1];
        float2 v0 = X2[(long)g_esrc[j] * 32 + lane];
        float2 v1 = X2[(long)g_esrc[j + 1] * 32 + lane];
        a0.x = fmaf(w0, v0.x, a0.x); a0.y = fmaf(w0, v0.y, a0.y);
        a1.x = fmaf(w1, v1.x, a1.x); a1.y = fmaf(w1, v1.y, a1.y);
    }
    if (j < e) {
        float w0 = g_ew[j];
        float2 v0 = X2[(long)g_esrc[j] * 32 + lane];
        a0.x = fmaf(w0, v0.x, a0.x); a0.y = fmaf(w0, v0.y, a0.y);
    }
    a0.x += a1.x; a0.y += a1.y;
    long o = (long)node * 32 + lane;
    if (SECOND) {
        float2 t = ((const float2*)T0)[o];
        a0.x = 2.f*a0.x - t.x; a0.y = 2.f*a0.y - t.y;
    }
    ((float2*)out)[o] = a0;
}

// ---------------- tf32 tensor-core fused 3-term GEMM ----------------
__device__ __forceinline__ unsigned f2tf32(float x) {
    unsigned u;
    asm("cvt.rna.tf32.f32 %0, %1;" : "=r"(u) : "f"(x));
    return u;
}

__device__ __forceinline__ void mma_tf32(float* c, const unsigned* a, unsigned b0, unsigned b1) {
    asm volatile(
        "mma.sync.aligned.m16n8k8.row.col.f32.tf32.tf32.f32 "
        "{%0,%1,%2,%3}, {%4,%5,%6,%7}, {%8,%9}, {%0,%1,%2,%3};"
        : "+f"(c[0]), "+f"(c[1]), "+f"(c[2]), "+f"(c[3])
        : "r"(a[0]), "r"(a[1]), "r"(a[2]), "r"(a[3]), "r"(b0), "r"(b1));
}

// out = relu([A0|A1|A2] @ W + bias), W is (3*FIN, FOUT) row-major.
template <int FIN, int FOUT>
__global__ void __launch_bounds__(256)
gemm3_mma(const float* __restrict__ A0, const float* __restrict__ A1,
          const float* __restrict__ A2, const float* __restrict__ W,
          const float* __restrict__ bias, float* __restrict__ out) {
    constexpr int BM = 128, BK = 32, NT = FOUT / 8;
    constexpr int ASTR = 36;            // bank-conflict-free frag reads (4*ly+lx)
    constexpr int BSTR = FOUT + 8;      // stride ≡ 8 (mod 32): 8*lx + ly conflict-free
    __shared__ unsigned As[BM * ASTR];
    __shared__ unsigned Bs[BK * BSTR];

    int tid = threadIdx.x;
    int w = tid >> 5, lane = tid & 31;
    int ly = lane >> 2, lx = lane & 3;
    int row0 = blockIdx.x * BM;

    float acc[NT][4];
#pragma unroll
    for (int t = 0; t < NT; t++)
#pragma unroll
        for (int i = 0; i < 4; i++) acc[t][i] = 0.f;

    for (int k0 = 0; k0 < 3 * FIN; k0 += BK) {
        const float* A = (k0 < FIN) ? A0 : ((k0 < 2 * FIN) ? A1 : A2);
        int kk = k0 % FIN;
        // A tile: 128x32 floats = 1024 float4, 4 per thread.
#pragma unroll
        for (int i = 0; i < 4; i++) {
            int idx = i * 256 + tid;
            int r = idx >> 3, k4 = (idx & 7) * 4;
            float4 v = make_float4(0.f, 0.f, 0.f, 0.f);
            int grow = row0 + r;
            if (grow < NN) v = *(const float4*)&A[(long)grow * FIN + kk + k4];
            As[r * ASTR + k4 + 0] = f2tf32(v.x);
            As[r * ASTR + k4 + 1] = f2tf32(v.y);
            As[r * ASTR + k4 + 2] = f2tf32(v.z);
            As[r * ASTR + k4 + 3] = f2tf32(v.w);
        }
        // B tile: 32xFOUT floats, contiguous in W.
#pragma unroll
        for (int i = 0; i < (BK * FOUT / 4 + 255) / 256; i++) {
            int idx = i * 256 + tid;
            if (idx < BK * FOUT / 4) {
                int r = idx / (FOUT / 4);
                int n4 = (idx % (FOUT / 4)) * 4;
                float4 v = *(const float4*)&W[(long)(k0 + r) * FOUT + n4];
                Bs[r * BSTR + n4 + 0] = f2tf32(v.x);
                Bs[r * BSTR + n4 + 1] = f2tf32(v.y);
                Bs[r * BSTR + n4 + 2] = f2tf32(v.z);
                Bs[r * BSTR + n4 + 3] = f2tf32(v.w);
            }
        }
        __syncthreads();
#pragma unroll
        for (int c = 0; c < 4; c++) {
            unsigned a[4];
            int ar = w * 16 + ly;
            int ak = c * 8 + lx;
            a[0] = As[ar * ASTR + ak];
            a[1] = As[(ar + 8) * ASTR + ak];
            a[2] = As[ar * ASTR + ak + 4];
            a[3] = As[(ar + 8) * ASTR + ak + 4];
#pragma unroll
            for (int t = 0; t < NT; t++) {
                int bn = t * 8 + ly;
                unsigned b0 = Bs[(c * 8 + lx) * BSTR + bn];
                unsigned b1 = Bs[(c * 8 + lx + 4) * BSTR + bn];
                mma_tf32(acc[t], a, b0, b1);
            }
        }
        __syncthreads();
    }
    // epilogue: bias + relu
    int r0 = row0 + w * 16 + ly;
#pragma unroll
    for (int t = 0; t < NT; t++) {
        int col = t * 8 + lx * 2;
        float bv0 = bias[col], bv1 = bias[col + 1];
        if (r0 < NN) {
            float2 v = make_float2(fmaxf(acc[t][0] + bv0, 0.f), fmaxf(acc[t][1] + bv1, 0.f));
            *(float2*)&out[(long)r0 * FOUT + col] = v;
        }
        if (r0 + 8 < NN) {
            float2 v = make_float2(fmaxf(acc[t][2] + bv0, 0.f), fmaxf(acc[t][3] + bv1, 0.f));
            *(float2*)&out[(long)(r0 + 8) * FOUT + col] = v;
        }
    }
}

// ---------------- pooling (batch is sorted -> run-length local accumulation) ----------------
#define POOL_NPB 256
__global__ void __launch_bounds__(256)
pool_kernel(const int* __restrict__ batch) {
    int t = threadIdx.x;
    int f = t & 31;
    int sub = t >> 5;   // 0..7
    int g_cur = -1;
    float acc = 0.f, cnt = 0.f;
    for (int i = 0; i < POOL_NPB / 8; i++) {
        int n = blockIdx.x * POOL_NPB + sub + i * 8;
        if (n >= NN) break;
        int g = batch[n];
        if (g != g_cur) {
            if (g_cur >= 0) {
                atomicAdd(&g_pool[g_cur * 32 + f], acc);
                if (f == 0) atomicAdd(&g_cntg[g_cur], cnt);
            }
            g_cur = g; acc = 0.f; cnt = 0.f;
        }
        acc += g_H3[(long)n * 32 + f];
        cnt += 1.f;
    }
    if (g_cur >= 0) {
        atomicAdd(&g_pool[g_cur * 32 + f], acc);
        if (f == 0) atomicAdd(&g_cntg[g_cur], cnt);
    }
}

__global__ void final_kernel(const float* __restrict__ Wl, const float* __restrict__ bl,
                             float* __restrict__ out) {
    int t = threadIdx.x;
    if (t >= GG * 2) return;
    int g = t >> 1, c = t & 1;
    float cnt = fmaxf(g_cntg[g], 1.f);
    float inv = 1.f / cnt;
    float s = bl[c];
#pragma unroll
    for (int f = 0; f < 32; f++) s += (g_pool[g * 32 + f] * inv) * Wl[f * 2 + c];
    out[g * 2 + c] = s;
}

// ---------------- driver ----------------
extern "C" void kernel_launch(void* const* d_in, const int* in_sizes, int n_in,
                              void* d_out, int out_size) {
    const float* x     = (const float*)d_in[0];
    const int*   ei    = (const int*)d_in[1];
    const float* ea    = (const float*)d_in[2];
    const int*   batch = (const int*)d_in[3];
    const float* W1 = (const float*)d_in[4];
    const float* b1 = (const float*)d_in[5];
    const float* W2 = (const float*)d_in[6];
    const float* b2 = (const float*)d_in[7];
    const float* W3 = (const float*)d_in[8];
    const float* b3 = (const float*)d_in[9];
    const float* Wl = (const float*)d_in[10];
    const float* bl = (const float*)d_in[11];
    float* out = (float*)d_out;

    const int* src = ei;
    const int* dst = ei + EE;

    float *T1, *T2, *H1, *H2, *H3;
    cudaGetSymbolAddress((void**)&T1, g_T1);
    cudaGetSymbolAddress((void**)&T2, g_T2);
    cudaGetSymbolAddress((void**)&H1, g_H1);
    cudaGetSymbolAddress((void**)&H2, g_H2);
    cudaGetSymbolAddress((void**)&H3, g_H3);

    int nb = (NN + 255) / 256;
    int eb = (EE + 255) / 256;
    int pb = (NN + 7) / 8;          // warp-per-node prop grid
    int gb = (NN + 127) / 128;      // gemm grid

    zero_kernel<<<nb, 256>>>();
    edge_deg_kernel<<<eb, 256>>>(src, dst, ea);
    dinv_kernel<<<nb, 256>>>();
    scan1_kernel<<<NBLK, SCAN_B>>>();
    scan2_kernel<<<1, 128>>>();
    scan3_kernel<<<nb, 256>>>();
    edge_scatter_kernel<<<eb, 256>>>(src, dst, ea);

    // Layer 1: 160 -> 128
    prop160_kernel<false><<<pb, 256>>>(x, nullptr, T1);
    prop160_kernel<true ><<<pb, 256>>>(T1, x, T2);
    gemm3_mma<160, 128><<<gb, 256>>>(x, T1, T2, W1, b1, H1);

    // Layer 2: 128 -> 64
    prop128_kernel<false><<<pb, 256>>>(H1, nullptr, T1);
    prop128_kernel<true ><<<pb, 256>>>(T1, H1, T2);
    gemm3_mma<128, 64><<<gb, 256>>>(H1, T1, T2, W2, b2, H2);

    // Layer 3: 64 -> 32
    prop64_kernel<false><<<pb, 256>>>(H2, nullptr, T1);
    prop64_kernel<true ><<<pb, 256>>>(T1, H2, T2);
    gemm3_mma<64, 32><<<gb, 256>>>(H2, T1, T2, W3, b3, H3);

    // Pool + linear
    pool_kernel<<<(NN + POOL_NPB - 1) / POOL_NPB, 256>>>(batch);
    final_kernel<<<1, 256>>>(Wl, bl, out);
}